// round 1
// baseline (speedup 1.0000x reference)
#include <cuda_runtime.h>
#include <math.h>

#define BATCH 32
#define T 1024
#define DIM 64
#define NDIAG (2 * T - 1)   // 2047

// Scratch: cost^2 in diagonal-major layout: g_costD[b][d][i] = cost(i, d-i)^2
__device__ float g_costD[(size_t)BATCH * NDIAG * T];
__device__ float g_dists[BATCH];

// ---------------------------------------------------------------------------
// Kernel A: squared pairwise distances, written diag-major.
// Block: 256 threads, computes a 64(i) x 64(j) tile for one batch.
// ---------------------------------------------------------------------------
__global__ __launch_bounds__(256) void cost_kernel(const float* __restrict__ a,
                                                   const float* __restrict__ b_) {
    __shared__ float sm[2 * 64 * 65];       // As | Bs, later reused as Cs (64x66)
    __shared__ float na_s[64], nb_s[64];
    float* As = sm;
    float* Bs = sm + 64 * 65;

    const int batch = blockIdx.z;
    const int i0 = blockIdx.x * 64;
    const int j0 = blockIdx.y * 64;
    const float* ab = a  + (size_t)batch * T * DIM;
    const float* bb = b_ + (size_t)batch * T * DIM;
    const int tid = threadIdx.x;

    // Load 64x64 a-tile and b-tile (float4 from gmem, scalar into padded smem)
    for (int v = tid; v < 64 * 16; v += 256) {
        int row = v >> 4, kq = v & 15;
        float4 va = *(const float4*)(ab + (size_t)(i0 + row) * DIM + kq * 4);
        float4 vb = *(const float4*)(bb + (size_t)(j0 + row) * DIM + kq * 4);
        int base = row * 65 + kq * 4;
        As[base + 0] = va.x; As[base + 1] = va.y; As[base + 2] = va.z; As[base + 3] = va.w;
        Bs[base + 0] = vb.x; Bs[base + 1] = vb.y; Bs[base + 2] = vb.z; Bs[base + 3] = vb.w;
    }
    __syncthreads();

    // Row norms (threads 0..127, one row each; conflict-free: (tid*65+k)%32 distinct)
    if (tid < 128) {
        const float* src = (tid < 64) ? &As[tid * 65] : &Bs[(tid - 64) * 65];
        float s = 0.f;
#pragma unroll
        for (int k = 0; k < DIM; k++) s += src[k] * src[k];
        if (tid < 64) na_s[tid] = s; else nb_s[tid - 64] = s;
    }
    __syncthreads();

    // 4x4 register micro-tile per thread
    const int tx = tid & 15, ty = tid >> 4;
    float acc[4][4];
#pragma unroll
    for (int r = 0; r < 4; r++)
#pragma unroll
        for (int c = 0; c < 4; c++) acc[r][c] = 0.f;

#pragma unroll 8
    for (int k = 0; k < DIM; k++) {
        float af[4], bf[4];
#pragma unroll
        for (int r = 0; r < 4; r++) af[r] = As[(ty * 4 + r) * 65 + k];
#pragma unroll
        for (int c = 0; c < 4; c++) bf[c] = Bs[(tx * 4 + c) * 65 + k];
#pragma unroll
        for (int r = 0; r < 4; r++)
#pragma unroll
            for (int c = 0; c < 4; c++) acc[r][c] += af[r] * bf[c];
    }
    __syncthreads();   // done with As/Bs; reuse as Cs

    float* Cs = sm;    // 64 x 66 (padded)
#pragma unroll
    for (int r = 0; r < 4; r++) {
        float na = na_s[ty * 4 + r];
#pragma unroll
        for (int c = 0; c < 4; c++) {
            float sq = na + nb_s[tx * 4 + c] - 2.0f * acc[r][c];
            Cs[(ty * 4 + r) * 66 + (tx * 4 + c)] = fmaxf(sq, 1e-12f);
        }
    }
    __syncthreads();

    // Write diag-major: d = i0+j0+dd, coalesced over ii at fixed dd
    const size_t outbase = ((size_t)batch * NDIAG + (i0 + j0)) * T + i0;
    for (int v = tid; v < 127 * 64; v += 256) {
        int dd = v >> 6, ii = v & 63;
        int jj = dd - ii;
        if (jj >= 0 && jj < 64)
            g_costD[outbase + (size_t)dd * T + ii] = Cs[ii * 66 + jj];
    }
}

// ---------------------------------------------------------------------------
// Kernel DP: anti-diagonal wavefront, one CTA per batch, thread i = row i.
// 3 rotating smem diagonal buffers with +INF sentinels; cost streamed through
// an 8-deep register FIFO (manual unroll) to hide DRAM latency.
// ---------------------------------------------------------------------------
__global__ __launch_bounds__(1024) void dp_kernel() {
    __shared__ float buf0[T + 1], buf1[T + 1], buf2[T + 1];
    const int i = threadIdx.x;
    const int b = blockIdx.x;
    const float INFV = __int_as_float(0x7f800000);

    buf0[i + 1] = INFV; buf1[i + 1] = INFV; buf2[i + 1] = INFV;
    if (i == 0) { buf0[0] = INFV; buf1[0] = INFV; buf2[0] = INFV; }

    const float* costB = g_costD + (size_t)b * NDIAG * T + i;   // column i
    float* cur = buf0; float* dm1 = buf1; float* dm2 = buf2;

    // d = 0 special case (min of empty set would be INF otherwise)
    if (i == 0) cur[1] = costB[0];
    __syncthreads();
    { float* t = dm2; dm2 = dm1; dm1 = cur; cur = t; }

    // Preload cost for d = 1..8
    float r0 = costB[(size_t)1 * T], r1 = costB[(size_t)2 * T],
          r2 = costB[(size_t)3 * T], r3 = costB[(size_t)4 * T],
          r4 = costB[(size_t)5 * T], r5 = costB[(size_t)6 * T],
          r6 = costB[(size_t)7 * T], r7 = costB[(size_t)8 * T];

#define DP_STEP(K, RK)                                                        \
    {                                                                         \
        int d = dbase + (K);                                                  \
        if (d <= 2046) {                                                      \
            float cv = RK;                                                    \
            int dn = d + 8; if (dn > 2046) dn = 2046;                         \
            RK = costB[(size_t)dn * T];                                       \
            if (i <= d && i >= d - (T - 1)) {                                 \
                float up = dm1[i];                                            \
                float lf = dm1[i + 1];                                        \
                float dg = dm2[i];                                            \
                cur[i + 1] = fmaxf(cv, fminf(fminf(up, lf), dg));             \
            }                                                                 \
            __syncthreads();                                                  \
            float* tt = dm2; dm2 = dm1; dm1 = cur; cur = tt;                  \
        }                                                                     \
    }

    for (int dbase = 1; dbase <= 2046; dbase += 8) {
        DP_STEP(0, r0) DP_STEP(1, r1) DP_STEP(2, r2) DP_STEP(3, r3)
        DP_STEP(4, r4) DP_STEP(5, r5) DP_STEP(6, r6) DP_STEP(7, r7)
    }
#undef DP_STEP

    // dm1 now holds diagonal 2046; result at (1023,1023) -> slot [1024]
    if (i == 0) g_dists[b] = sqrtf(dm1[T]);
}

// ---------------------------------------------------------------------------
// Kernel F: mean of 32 per-batch distances.
// ---------------------------------------------------------------------------
__global__ void finish_kernel(float* __restrict__ out) {
    int t = threadIdx.x;
    float v = g_dists[t];
#pragma unroll
    for (int o = 16; o; o >>= 1) v += __shfl_xor_sync(0xffffffffu, v, o);
    if (t == 0) out[0] = v * (1.0f / BATCH);
}

extern "C" void kernel_launch(void* const* d_in, const int* in_sizes, int n_in,
                              void* d_out, int out_size) {
    const float* pred = (const float*)d_in[0];
    const float* targ = (const float*)d_in[1];
    cost_kernel<<<dim3(T / 64, T / 64, BATCH), 256>>>(pred, targ);
    dp_kernel<<<BATCH, 1024>>>();
    finish_kernel<<<1, 32>>>((float*)d_out);
}

// round 3
// speedup vs baseline: 1.6462x; 1.6462x over previous
#include <cuda_runtime.h>
#include <math.h>

#define BATCH 32
#define T     1024
#define DIM   64
#define NW    8            // DP warps per batch (128 rows each)
#define STEPS 1056         // 33 chunks of 32 (covers 1024+31 wavefront steps)
#define SPAD  1064         // STEPS + 8 prefetch pad
#define HANDW 1090         // handoff row width (1026 needed + slack for prefetch reads)

// Scratch: cost^2 in warp-skewed layout: g_cst[((b*NW+w)*SPAD + s)*128 + i],
// where i = row within warp block (0..127), s = j + (i>>2)  (lane skew).
__device__ float g_cst[(size_t)BATCH * NW * SPAD * 128];
__device__ float g_na[BATCH * T];
__device__ float g_nb[BATCH * T];
__device__ float g_dists[BATCH];

// ---------------------------------------------------------------------------
// Row squared-norms: one warp per row.
// ---------------------------------------------------------------------------
__global__ __launch_bounds__(256) void norm_kernel(const float* __restrict__ a,
                                                   const float* __restrict__ b) {
    int gw   = blockIdx.x * 8 + (threadIdx.x >> 5);   // 0..65535
    int lane = threadIdx.x & 31;
    int which = gw >> 15;                              // 0: a, 1: b
    int row   = gw & 32767;                            // b*T + i
    const float* src = (which ? b : a) + (size_t)row * DIM + lane * 2;
    float2 v = *(const float2*)src;
    float s = v.x * v.x + v.y * v.y;
#pragma unroll
    for (int o = 16; o; o >>= 1) s += __shfl_xor_sync(0xffffffffu, s, o);
    if (lane == 0) (which ? g_nb : g_na)[row] = s;
}

// ---------------------------------------------------------------------------
// INF-fill for skew slots never written by cost_kernel (s<32 or s>=1024 part).
// cost_kernel runs after and overwrites the valid entries.
// ---------------------------------------------------------------------------
__global__ void fill_kernel() {
    const float INFV = __int_as_float(0x7f800000);
    size_t base = (size_t)blockIdx.x * SPAD * 128;    // one (b,w) per CTA
    const int NS = 32 + (SPAD - 1024);                // 72 s-slots
    for (int v = threadIdx.x; v < NS * 128; v += blockDim.x) {
        int sr = v >> 7, i = v & 127;
        int s = (sr < 32) ? sr : (1024 + sr - 32);
        g_cst[base + (size_t)s * 128 + i] = INFV;
    }
}

// ---------------------------------------------------------------------------
// Cost kernel: squared pairwise distances via GEMM, 128(i) x 32(j) tile,
// 128 threads, 8x4 register micro-tile. Output staged in smem, written in
// the warp-skewed layout with coalesced 512B rows.
// ---------------------------------------------------------------------------
__global__ __launch_bounds__(128) void cost_kernel(const float* __restrict__ A,
                                                   const float* __restrict__ B) {
    __shared__ float As[128 * 65];   // row-major, pad 65 (reused as Cs, stride 34)
    __shared__ float Bs[32 * 65];

    const int w  = blockIdx.x;       // warp-block (128 rows)
    const int j0 = blockIdx.y * 32;
    const int b  = blockIdx.z;
    const int tid = threadIdx.x;
    const int tx = tid & 7;          // 8  -> 4 cols each
    const int ty = tid >> 3;         // 16 -> 8 rows each

    const float* Ab = A + ((size_t)b * T + w * 128) * DIM;
    const float* Bb = B + ((size_t)b * T + j0) * DIM;

    // Load tiles (float4 gmem, scalar smem; ~2-way write conflicts)
    for (int v = tid; v < 128 * 16; v += 128) {
        int i = v >> 4, kq = v & 15;
        float4 va = *(const float4*)(Ab + (size_t)i * DIM + kq * 4);
        int base = i * 65 + kq * 4;
        As[base + 0] = va.x; As[base + 1] = va.y; As[base + 2] = va.z; As[base + 3] = va.w;
    }
    for (int v = tid; v < 32 * 16; v += 128) {
        int j = v >> 4, kq = v & 15;
        float4 vb = *(const float4*)(Bb + (size_t)j * DIM + kq * 4);
        int base = j * 65 + kq * 4;
        Bs[base + 0] = vb.x; Bs[base + 1] = vb.y; Bs[base + 2] = vb.z; Bs[base + 3] = vb.w;
    }
    __syncthreads();

    float acc[8][4];
#pragma unroll
    for (int r = 0; r < 8; r++)
#pragma unroll
        for (int c = 0; c < 4; c++) acc[r][c] = 0.f;

#pragma unroll 4
    for (int k = 0; k < DIM; k++) {
        float ar[8], br[4];
#pragma unroll
        for (int r = 0; r < 8; r++) ar[r] = As[(ty * 8 + r) * 65 + k];
#pragma unroll
        for (int c = 0; c < 4; c++) br[c] = Bs[(tx * 4 + c) * 65 + k];
#pragma unroll
        for (int r = 0; r < 8; r++)
#pragma unroll
            for (int c = 0; c < 4; c++) acc[r][c] += ar[r] * br[c];
    }
    __syncthreads();                 // As dead; reuse as Cs

    float* Cs = As;                  // [128][34]
    {
        float nar[8], nbr[4];
        const float* nap = g_na + b * T + w * 128 + ty * 8;
        const float* nbp = g_nb + b * T + j0 + tx * 4;
#pragma unroll
        for (int r = 0; r < 8; r++) nar[r] = nap[r];
#pragma unroll
        for (int c = 0; c < 4; c++) nbr[c] = nbp[c];
#pragma unroll
        for (int r = 0; r < 8; r++)
#pragma unroll
            for (int c = 0; c < 4; c++) {
                float sq = nar[r] + nbr[c] - 2.0f * acc[r][c];
                Cs[(ty * 8 + r) * 34 + (tx * 4 + c)] = fmaxf(sq, 1e-12f);
            }
    }
    __syncthreads();

    // Skewed write: slot [s][i] with s = j + (i>>2);  s_rel = j_rel + (i>>2)
    size_t obase = ((size_t)(b * NW + w) * SPAD + j0) * 128;
    const int i = tid;               // 128 threads = 128 rows
    const int sk = i >> 2;
#pragma unroll 1
    for (int sr = 0; sr < 63; sr++) {
        int jr = sr - sk;
        if (jr >= 0 && jr < 32)
            g_cst[obase + (size_t)sr * 128 + i] = Cs[i * 34 + jr];
    }
}

// ---------------------------------------------------------------------------
// DP kernel: warp-pipelined skewed wavefront. One CTA per batch, 8 warps,
// 4 rows per lane, lane l processes column j = s - l at step s.
// Cross-warp handoff via smem ring + chunked progress flags (no __syncthreads
// in the mainloop). Cost streamed through an 8-deep float4 register FIFO.
// ---------------------------------------------------------------------------
__global__ __launch_bounds__(256) void dp_kernel() {
    __shared__ float sm_hand[(NW + 1) * HANDW];     // row NW = all-INF dummy
    __shared__ volatile int progress[NW];
    const float INFV = __int_as_float(0x7f800000);

    const int tid = threadIdx.x, w = tid >> 5, lane = tid & 31;
    const int b = blockIdx.x;

    for (int v = tid; v < HANDW; v += 256) sm_hand[NW * HANDW + v] = INFV;
    if (lane == 0) { sm_hand[w * HANDW] = INFV; progress[w] = 0; }
    __syncthreads();

    const int wm1 = (w == 0) ? NW : (w - 1);
    const float* hrow = &sm_hand[wm1 * HANDW];      // producer row (or INF dummy)
    // u32 smem address of own handoff row slot for s=0 write (jj = s-30)
    unsigned wrow_addr;
    {
        unsigned base;
        asm("{ .reg .u64 t; cvta.to.shared.u64 t, %1; cvt.u32.u64 %0, t; }"
            : "=r"(base) : "l"(&sm_hand[w * HANDW]));
        wrow_addr = base - 30u * 4u;                // + s*4 gives slot jj = s-30
    }

    const float* cp = g_cst + (size_t)(b * NW + w) * SPAD * 128 + lane * 4;

    float4 f[8];
#pragma unroll
    for (int q = 0; q < 8; q++) f[q] = *(const float4*)(cp + (size_t)q * 128);

    float v0 = INFV, v1 = INFV, v2 = INFV, v3 = INFV, uprev = INFV;
    float hv = INFV;
    const bool fix0 = (w == 0) && (lane == 0);
    const unsigned p31 = (lane == 31) ? 1u : 0u;

    for (int t = 0; t < 33; t++) {
        if (w) {                                     // need producer chunk t+1 done
            int need = (t + 2 > 33) ? 33 : (t + 2);
            while (progress[w - 1] < need) { }
            __threadfence_block();
        }
        if (t == 0) hv = hrow[1];                    // up for s=0 (col j = s)

#pragma unroll
        for (int kk = 0; kk < 32; kk++) {
            const int s = t * 32 + kk;
            float4 c = f[kk & 7];
            f[kk & 7] = *(const float4*)(cp + (size_t)(s + 8) * 128);

            float u = __shfl_up_sync(0xffffffffu, v3, 1);
            u = (lane == 0) ? hv : u;
            hv = hrow[s + 2];                        // prefetch next step's up

            float m0 = fminf(v0, uprev);
            float n0 = fmaxf(c.x, fminf(u, m0));
            if (kk == 0) n0 = (fix0 && t == 0) ? c.x : n0;   // cell (0,0)
            float m1 = fminf(v1, v0);
            float n1 = fmaxf(c.y, fminf(n0, m1));
            float m2 = fminf(v2, v1);
            float n2 = fmaxf(c.z, fminf(n1, m2));
            float m3 = fminf(v3, v2);
            float n3 = fmaxf(c.w, fminf(n2, m3));
            v0 = n0; v1 = n1; v2 = n2; v3 = n3; uprev = u;

            // lane 31: publish bottom row (col j = s-31) at slot jj = s-30.
            // Guard s>=30 (jj>=0); jj==0 writes INF (v3 still INF) - harmless.
            unsigned pr = p31 & (s >= 30 ? 1u : 0u);
            unsigned addr = wrow_addr + (unsigned)s * 4u;
            asm volatile(
                "{ .reg .pred p; setp.ne.u32 p, %0, 0; @p st.shared.f32 [%1], %2; }"
                :: "r"(pr), "r"(addr), "f"(n3));
        }
        __syncwarp();
        __threadfence_block();
        if (lane == 0) progress[w] = t + 1;
    }
    __syncthreads();
    if (tid == 0) g_dists[b] = sqrtf(sm_hand[7 * HANDW + 1024]);
}

// ---------------------------------------------------------------------------
__global__ void finish_kernel(float* __restrict__ out) {
    int t = threadIdx.x;
    float v = g_dists[t];
#pragma unroll
    for (int o = 16; o; o >>= 1) v += __shfl_xor_sync(0xffffffffu, v, o);
    if (t == 0) out[0] = v * (1.0f / BATCH);
}

extern "C" void kernel_launch(void* const* d_in, const int* in_sizes, int n_in,
                              void* d_out, int out_size) {
    const float* pred = (const float*)d_in[0];
    const float* targ = (const float*)d_in[1];
    fill_kernel<<<BATCH * NW, 256>>>();
    norm_kernel<<<(BATCH * T * 2) / 8, 256>>>(pred, targ);
    cost_kernel<<<dim3(NW, T / 32, BATCH), 128>>>(pred, targ);
    dp_kernel<<<BATCH, 256>>>();
    finish_kernel<<<1, 32>>>((float*)d_out);
}

// round 4
// speedup vs baseline: 1.8295x; 1.1114x over previous
#include <cuda_runtime.h>
#include <cuda_fp16.h>
#include <math.h>

#define BATCH 32
#define T     1024
#define DIM   64
#define NW    8                 // DP warps per batch (128 rows each)
#define CH    16                // steps per chunk
#define NCH   72                // chunks: 72*16 = 1152 steps (need 1151)
#define STEPS (NCH * CH)
#define SPAD  (STEPS + 16)      // 1168 slots (16 = FIFO prefetch pad)
#define HANDW 1160              // handoff row width in halves (reads to s+3=1154)

// Scratch: cost^2 (fp16), per-ROW skewed: g_cst[((b*NW+w)*SPAD + s)*128 + i]
// holds cost[128w + i][s - i]; invalid cells = +INF.
__device__ __half g_cst[(size_t)BATCH * NW * SPAD * 128];
__device__ float g_na[BATCH * T];
__device__ float g_nb[BATCH * T];
__device__ float g_dists[BATCH];

__device__ __forceinline__ unsigned hmin2u(unsigned a, unsigned b) {
    __half2 r = __hmin2(*reinterpret_cast<__half2*>(&a), *reinterpret_cast<__half2*>(&b));
    return *reinterpret_cast<unsigned*>(&r);
}
__device__ __forceinline__ unsigned hmax2u(unsigned a, unsigned b) {
    __half2 r = __hmax2(*reinterpret_cast<__half2*>(&a), *reinterpret_cast<__half2*>(&b));
    return *reinterpret_cast<unsigned*>(&r);
}

// ---------------------------------------------------------------------------
// Row squared-norms: one warp per row.
// ---------------------------------------------------------------------------
__global__ __launch_bounds__(256) void norm_kernel(const float* __restrict__ a,
                                                   const float* __restrict__ b) {
    int gw   = blockIdx.x * 8 + (threadIdx.x >> 5);
    int lane = threadIdx.x & 31;
    int which = gw >> 15;
    int row   = gw & 32767;
    const float* src = (which ? b : a) + (size_t)row * DIM + lane * 2;
    float2 v = *(const float2*)src;
    float s = v.x * v.x + v.y * v.y;
#pragma unroll
    for (int o = 16; o; o >>= 1) s += __shfl_xor_sync(0xffffffffu, s, o);
    if (lane == 0) (which ? g_nb : g_na)[row] = s;
}

// ---------------------------------------------------------------------------
// INF-fill: slots [0,127) and [1024,SPAD) are fully INF'd; cost_kernel then
// overwrites all valid entries (runs after this).
// ---------------------------------------------------------------------------
__global__ void fill_kernel() {
    size_t base = (size_t)blockIdx.x * SPAD * 128;      // halves, one (b,w)/CTA
    const int NS = 127 + (SPAD - 1024);                 // 271 slots
    for (int v = threadIdx.x; v < NS * 64; v += blockDim.x) {
        int sr = v >> 6, wq = v & 63;
        int s = (sr < 127) ? sr : (1024 + sr - 127);
        ((unsigned*)(g_cst + base + (size_t)s * 128))[wq] = 0x7C007C00u;
    }
}

// ---------------------------------------------------------------------------
// Cost kernel: 128(i) x 32(j) tile, 128 threads, 8x4 micro-tile.
// Epilogue: fp16 results staged in smem, emitted to per-row-skewed layout
// with warp-per-slot coalesced u16 stores.
// ---------------------------------------------------------------------------
__global__ __launch_bounds__(128) void cost_kernel(const float* __restrict__ A,
                                                   const float* __restrict__ B) {
    __shared__ float As[128 * 65];    // reused as half Ch[128][34]
    __shared__ float Bs[32 * 65];

    const int w  = blockIdx.x;
    const int j0 = blockIdx.y * 32;
    const int b  = blockIdx.z;
    const int tid = threadIdx.x;
    const int tx = tid & 7;
    const int ty = tid >> 3;

    const float* Ab = A + ((size_t)b * T + w * 128) * DIM;
    const float* Bb = B + ((size_t)b * T + j0) * DIM;

    for (int v = tid; v < 128 * 16; v += 128) {
        int i = v >> 4, kq = v & 15;
        float4 va = *(const float4*)(Ab + (size_t)i * DIM + kq * 4);
        int base = i * 65 + kq * 4;
        As[base + 0] = va.x; As[base + 1] = va.y; As[base + 2] = va.z; As[base + 3] = va.w;
    }
    for (int v = tid; v < 32 * 16; v += 128) {
        int j = v >> 4, kq = v & 15;
        float4 vb = *(const float4*)(Bb + (size_t)j * DIM + kq * 4);
        int base = j * 65 + kq * 4;
        Bs[base + 0] = vb.x; Bs[base + 1] = vb.y; Bs[base + 2] = vb.z; Bs[base + 3] = vb.w;
    }
    __syncthreads();

    float acc[8][4];
#pragma unroll
    for (int r = 0; r < 8; r++)
#pragma unroll
        for (int c = 0; c < 4; c++) acc[r][c] = 0.f;

#pragma unroll 4
    for (int k = 0; k < DIM; k++) {
        float ar[8], br[4];
#pragma unroll
        for (int r = 0; r < 8; r++) ar[r] = As[(ty * 8 + r) * 65 + k];
#pragma unroll
        for (int c = 0; c < 4; c++) br[c] = Bs[(tx * 4 + c) * 65 + k];
#pragma unroll
        for (int r = 0; r < 8; r++)
#pragma unroll
            for (int c = 0; c < 4; c++) acc[r][c] += ar[r] * br[c];
    }
    __syncthreads();                 // As dead; reuse as Ch (halves)

    __half* Ch = (__half*)As;        // [128][34] halves
    {
        float nar[8], nbr[4];
        const float* nap = g_na + b * T + w * 128 + ty * 8;
        const float* nbp = g_nb + b * T + j0 + tx * 4;
#pragma unroll
        for (int r = 0; r < 8; r++) nar[r] = nap[r];
#pragma unroll
        for (int c = 0; c < 4; c++) nbr[c] = nbp[c];
#pragma unroll
        for (int r = 0; r < 8; r++)
#pragma unroll
            for (int c = 0; c < 4; c++) {
                float sq = nar[r] + nbr[c] - 2.0f * acc[r][c];
                Ch[(ty * 8 + r) * 34 + (tx * 4 + c)] = __float2half_rn(fmaxf(sq, 1e-12f));
            }
    }
    __syncthreads();

    // Skewed emit: slot s = j + i (i = local row). Tile covers sr = s - j0 in
    // [0,159). One warp per slot row: lanes = 32 consecutive i's, coalesced.
    const int wid = tid >> 5, lane = tid & 31;
    size_t sbase = ((size_t)(b * NW + w) * SPAD + j0) * 128;
#pragma unroll 1
    for (int it = 0; it < 40; it++) {
        int sr = it * 4 + wid;
        if (sr < 159) {
            int i0s = sr - 31; if (i0s < 0) i0s = 0;
            int i = i0s + lane;
            int jr = sr - i;
            if (i < 128 && jr >= 0 && jr < 32)
                g_cst[sbase + (size_t)sr * 128 + i] = Ch[i * 34 + jr];
        }
    }
}

// ---------------------------------------------------------------------------
// DP kernel: per-ROW-skewed systolic wavefront, fp16x2.
// Lane l owns rows 4l..4l+3 (two half2: hA=(r0,r1), hB=(r2,r3)); row r at
// step s handles column s-r. All cells at step s depend only on steps
// s-1/s-2 -> loop-carried chain = one shfl (26cy). Cross-warp handoff via
// fp16 smem rows + chunked progress flags. Cost via 16-deep uint2 FIFO.
// ---------------------------------------------------------------------------
__global__ __launch_bounds__(256) void dp_kernel() {
    __shared__ __align__(8) unsigned short hand[(NW + 1) * HANDW];
    __shared__ volatile int progress[NW];

    const int tid = threadIdx.x, w = tid >> 5, lane = tid & 31;
    const int b = blockIdx.x;

    for (int v = tid; v < (NW + 1) * HANDW / 2; v += 256)
        ((unsigned*)hand)[v] = 0x7C007C00u;
    if (lane == 0) progress[w] = 0;
    __syncthreads();

    const unsigned short* hrow = &hand[((w == 0) ? NW : (w - 1)) * HANDW];
    unsigned wrow;   // smem u32 addr for publishes: +s*2 -> hand[w][s-127]
    {
        unsigned base;
        asm("{ .reg .u64 t; cvta.to.shared.u64 t, %1; cvt.u32.u64 %0, t; }"
            : "=r"(base) : "l"(&hand[w * HANDW]));
        wrow = base - 254u;
    }

    const __half* cp = g_cst + (size_t)(b * NW + w) * SPAD * 128 + lane * 4;
    uint2 f[16];
#pragma unroll
    for (int q = 0; q < 16; q++) f[q] = *(const uint2*)(cp + (size_t)q * 128);

    const unsigned INF2 = 0x7C007C00u;
    unsigned hA = INF2, hB = INF2, vm1A = INF2, vm1B = INF2, wm1A = INF2, wm1B = INF2;
    unsigned hv1 = 0x7C000000u, hv2 = 0x7C000000u;   // hand vals packed <<16
    const bool isl0 = (lane == 0);
    const bool fix0 = (w == 0) && isl0;
    const unsigned p31 = (lane == 31) ? 1u : 0u;

    for (int t = 0; t < NCH; t++) {
        if (w) {
            int need = t + 10; if (need > NCH) need = NCH;
            while (progress[w - 1] < need) __nanosleep(40);
            __threadfence_block();
        }
        if (t == 0) {
            unsigned h0 = hrow[0], h1 = hrow[1], h2 = hrow[2];
            if (isl0) vm1A = h0 | 0x7C000000u;  // row0 up@s=0 = hand[0], y=INF
            hv1 = h1 << 16; hv2 = h2 << 16;
        }
#pragma unroll
        for (int kk = 0; kk < CH; kk++) {
            const int s = t * CH + kk;
            uint2 cw = f[kk];
            f[kk] = *(const uint2*)(cp + (size_t)(s + 16) * 128);

            unsigned nA = hmax2u(cw.x, hmin2u(hmin2u(vm1A, hA), wm1A));
            unsigned nB = hmax2u(cw.y, hmin2u(hmin2u(vm1B, hB), wm1B));
            if (kk == 0 && t == 0) {
                if (fix0) nA = (nA & 0xFFFF0000u) | (cw.x & 0xFFFFu);  // cell(0,0)
            }
            // lane31 publishes row 127 (nB high half) at column s-127
            unsigned pr = p31 & (unsigned)(s >= 127);
            asm volatile(
                "{ .reg .pred p; setp.ne.u32 p, %0, 0; @p st.shared.u16 [%1], %2; }"
                :: "r"(pr), "r"(wrow + (unsigned)s * 2),
                   "h"((unsigned short)(nB >> 16)));
            // build next step's shifted vectors
            unsigned sh = __shfl_up_sync(0xffffffffu, nB, 1);
            if (isl0) sh = hv1;                 // hand[s+1] in high half
            hv1 = hv2;
            hv2 = ((unsigned)hrow[s + 3]) << 16;
            wm1A = vm1A; wm1B = vm1B;
            vm1A = __byte_perm(sh, nA, 0x5432); // (v_{4l-1}, v_{4l})
            vm1B = __byte_perm(nA, nB, 0x5432); // (v_{4l+1}, v_{4l+2})
            hA = nA; hB = nB;
        }
        __syncwarp();
        __threadfence_block();
        if (lane == 0) progress[w] = t + 1;
    }
    __syncthreads();
    if (tid == 0)
        g_dists[b] = sqrtf(__half2float(__ushort_as_half(hand[7 * HANDW + 1023])));
}

// ---------------------------------------------------------------------------
__global__ void finish_kernel(float* __restrict__ out) {
    int t = threadIdx.x;
    float v = g_dists[t];
#pragma unroll
    for (int o = 16; o; o >>= 1) v += __shfl_xor_sync(0xffffffffu, v, o);
    if (t == 0) out[0] = v * (1.0f / BATCH);
}

extern "C" void kernel_launch(void* const* d_in, const int* in_sizes, int n_in,
                              void* d_out, int out_size) {
    const float* pred = (const float*)d_in[0];
    const float* targ = (const float*)d_in[1];
    fill_kernel<<<BATCH * NW, 256>>>();
    norm_kernel<<<(BATCH * T * 2) / 8, 256>>>(pred, targ);
    cost_kernel<<<dim3(NW, T / 32, BATCH), 128>>>(pred, targ);
    dp_kernel<<<BATCH, 256>>>();
    finish_kernel<<<1, 32>>>((float*)d_out);
}